// round 6
// baseline (speedup 1.0000x reference)
#include <cuda_runtime.h>
#include <cuda_bf16.h>
#include <cstdint>
#include <math.h>

#define N_NODES 32768
#define D 512
#define L 8
#define LN_EPS 1e-5f

// ---------------- helpers ----------------------------------------------------
__device__ __forceinline__ uint32_t smem_u32(const void* p) {
    uint32_t a;
    asm("{ .reg .u64 t; cvta.to.shared.u64 t, %1; cvt.u32.u64 %0, t; }" : "=r"(a) : "l"(p));
    return a;
}
__device__ __forceinline__ uint32_t pbf2(float lo, float hi) {  // lo -> bits[0:16)
    uint32_t r;
    asm("cvt.rn.bf16x2.f32 %0, %1, %2;" : "=r"(r) : "f"(hi), "f"(lo));
    return r;
}
__device__ __forceinline__ float tanh_fast(float x) {
    float y;
    asm("tanh.approx.f32 %0, %1;" : "=f"(y) : "f"(x));
    return y;
}
__device__ __forceinline__ void ldm_x4(uint32_t& r0, uint32_t& r1, uint32_t& r2,
                                       uint32_t& r3, uint32_t addr) {
    asm volatile("ldmatrix.sync.aligned.m8n8.x4.shared.b16 {%0,%1,%2,%3}, [%4];"
                 : "=r"(r0), "=r"(r1), "=r"(r2), "=r"(r3) : "r"(addr));
}
__device__ __forceinline__ void mma16816(float* d, const uint32_t* a, const uint32_t* b) {
    asm volatile(
        "mma.sync.aligned.m16n8k16.row.col.f32.bf16.bf16.f32 "
        "{%0,%1,%2,%3}, {%4,%5,%6,%7}, {%8,%9}, {%0,%1,%2,%3};"
        : "+f"(d[0]), "+f"(d[1]), "+f"(d[2]), "+f"(d[3])
        : "r"(a[0]), "r"(a[1]), "r"(a[2]), "r"(a[3]), "r"(b[0]), "r"(b[1]));
}

// ---------------- scratch -----------------------------------------------------
__device__ __align__(16) float g_h[(size_t)N_NODES * D];
__device__ __align__(16) float g_A[(size_t)N_NODES * D];
__device__ int   g_perm[N_NODES];
__device__ int   g_counts[L];
__device__ int   g_offs[L];
__device__ int   g_cursor[L];
__device__ float g_means[L * D];
__device__ float g_Bb[L * D];
// pre-transposed bf16 weight halves: [mat][n][k], mat 0..7 proj, 8 W1a, 9 Wout
__device__ __align__(16) __nv_bfloat16 g_bth[10 * 512 * 512];
__device__ __align__(16) __nv_bfloat16 g_btl[10 * 512 * 512];

// ---------------- bucketing ----------------------------------------------------
__global__ void reset_kernel() {
    int idx = blockIdx.x * blockDim.x + threadIdx.x;
    if (idx < L) g_counts[idx] = 0;
    if (idx < L * D) g_means[idx] = 0.f;
}
__global__ void hist_kernel(const int* __restrict__ levels) {
    __shared__ int h[L];
    if (threadIdx.x < L) h[threadIdx.x] = 0;
    __syncthreads();
    int i = blockIdx.x * blockDim.x + threadIdx.x;
    if (i < N_NODES) atomicAdd(&h[levels[i]], 1);
    __syncthreads();
    if (threadIdx.x < L) atomicAdd(&g_counts[threadIdx.x], h[threadIdx.x]);
}
__global__ void scan_kernel() {
    int o = 0;
    for (int l = 0; l < L; l++) { g_offs[l] = o; g_cursor[l] = o; o += g_counts[l]; }
}
__global__ void scatter_kernel(const int* __restrict__ levels) {
    int i = blockIdx.x * blockDim.x + threadIdx.x;
    if (i < N_NODES) {
        int p = atomicAdd(&g_cursor[levels[i]], 1);
        g_perm[p] = i;
    }
}

// ---------------- weight prep: transpose + bf16 split ---------------------------
__global__ void prep_b_kernel(const float* __restrict__ Wp,
                              const float* __restrict__ W1a,
                              const float* __restrict__ Wout) {
    int idx = blockIdx.x * 256 + threadIdx.x;
    if (idx >= 10 * 262144) return;
    int mat = idx >> 18;
    int rem = idx & 262143;
    int n = rem >> 9;
    int k = rem & 511;
    const float* src = (mat < 8) ? (Wp + ((size_t)mat << 18)) : (mat == 8 ? W1a : Wout);
    float v = src[(size_t)k * 512 + n];
    __nv_bfloat16 h = __float2bfloat16(v);
    g_bth[idx] = h;
    g_btl[idx] = __float2bfloat16(v - __bfloat162float(h));
}

// ---------------- HMMA GEMM: Y[M x 512] = X[M x 512] @ W (bf16 split) ----------
// MODE 0: grouped per level: X = node_features gathered via perm, +b_proj[l] -> g_h
// MODE 1: X = g_h @ W1a -> g_A
// MODE 2: X = g_h @ Wout + bout -> g_A (LN done separately)
#define NCHK 16          // 512 / 32
#define ROWH 40          // 32 + 8 pad halves per smem row
#define MATB (128 * ROWH)       // halves per matrix
#define BUFB (4 * MATB * 2)     // bytes per buffer (Ah, Al, Bh, Bl)
#define SMEM_TOT (2 * BUFB)     // 81920 bytes

template <int MODE>
__global__ void __launch_bounds__(256, 1)
gemm_hmma(const float* __restrict__ Xin, const float* __restrict__ biasBase)
{
    const int lvl  = (MODE == 0) ? blockIdx.z : 0;
    const int cnt  = (MODE == 0) ? g_counts[lvl] : N_NODES;
    const int base = (MODE == 0) ? g_offs[lvl] : 0;
    const int m0 = blockIdx.y * 128;
    if (m0 >= cnt) return;
    const int n0 = blockIdx.x * 128;

    extern __shared__ __align__(16) char smem[];
    __nv_bfloat16* s = reinterpret_cast<__nv_bfloat16*>(smem);
    const uint32_t s32 = smem_u32(smem);

    const int t = threadIdx.x;
    const int wid = t >> 5, lane = t & 31;

    const int mat = (MODE == 0) ? lvl : (MODE == 1 ? 8 : 9);
    const __nv_bfloat16* __restrict__ BhG = g_bth + ((size_t)mat << 18);
    const __nv_bfloat16* __restrict__ BlG = g_btl + ((size_t)mat << 18);
    const float* __restrict__ X = (MODE == 0) ? Xin : g_h;

    // A-load mapping: thread pair per row
    const int a_row = t >> 1;
    const int a_kh  = (t & 1) * 16;
    long arow = -1;
    if (m0 + a_row < cnt)
        arow = (MODE == 0) ? (long)g_perm[base + m0 + a_row] : (long)(m0 + a_row);

    // B-load mapping: idx -> (row n, 16B seg)
    const int b_row0 = (t + 0)   >> 2, b_seg0 = (t + 0)   & 3;
    const int b_row1 = (t + 256) >> 2, b_seg1 = (t + 256) & 3;

    // warp tiles
    const int mrow0 = (wid >> 2) * 64;
    const int ncol0 = (wid & 3) * 32;
    // ldmatrix lane addressing components
    const int a_rl = lane & 15;
    const int a_kl = (lane >> 4) * 8;
    const int b_nl = (lane >> 4) * 8 + (lane & 7);
    const int b_kl = ((lane >> 3) & 1) * 8;

    float acc[4][4][4];
#pragma unroll
    for (int i = 0; i < 4; i++)
#pragma unroll
        for (int j = 0; j < 4; j++)
#pragma unroll
            for (int q = 0; q < 4; q++) acc[i][j][q] = 0.f;

    float4 av[4];
    uint4 bvh[2], bvl[2];

    // ---- load chunk 0 into regs ----
    {
        const float* xp = (arow >= 0) ? (X + arow * (long)D + a_kh) : nullptr;
#pragma unroll
        for (int j = 0; j < 4; j++)
            av[j] = xp ? *reinterpret_cast<const float4*>(xp + j * 4)
                       : make_float4(0.f, 0.f, 0.f, 0.f);
        bvh[0] = *reinterpret_cast<const uint4*>(BhG + (size_t)(n0 + b_row0) * 512 + b_seg0 * 8);
        bvh[1] = *reinterpret_cast<const uint4*>(BhG + (size_t)(n0 + b_row1) * 512 + b_seg1 * 8);
        bvl[0] = *reinterpret_cast<const uint4*>(BlG + (size_t)(n0 + b_row0) * 512 + b_seg0 * 8);
        bvl[1] = *reinterpret_cast<const uint4*>(BlG + (size_t)(n0 + b_row1) * 512 + b_seg1 * 8);
    }

    for (int c = 0; c < NCHK; c++) {
        const int p = c & 1;
        __nv_bfloat16* sAh = s + p * (4 * MATB);
        __nv_bfloat16* sAl = sAh + MATB;
        __nv_bfloat16* sBh = sAh + 2 * MATB;
        __nv_bfloat16* sBl = sAh + 3 * MATB;

        // ---- store regs (chunk c) into buffer p ----
        {
            uint32_t hij[8], lij[8];
#pragma unroll
            for (int j = 0; j < 4; j++) {
                float4 v = av[j];
                float hx = __bfloat162float(__float2bfloat16(v.x));
                float hy = __bfloat162float(__float2bfloat16(v.y));
                float hz = __bfloat162float(__float2bfloat16(v.z));
                float hw = __bfloat162float(__float2bfloat16(v.w));
                hij[j * 2 + 0] = pbf2(hx, hy);
                hij[j * 2 + 1] = pbf2(hz, hw);
                lij[j * 2 + 0] = pbf2(v.x - hx, v.y - hy);
                lij[j * 2 + 1] = pbf2(v.z - hz, v.w - hw);
            }
            __nv_bfloat16* ap = sAh + a_row * ROWH + a_kh;
            *reinterpret_cast<uint4*>(ap)     = make_uint4(hij[0], hij[1], hij[2], hij[3]);
            *reinterpret_cast<uint4*>(ap + 8) = make_uint4(hij[4], hij[5], hij[6], hij[7]);
            __nv_bfloat16* lp = sAl + a_row * ROWH + a_kh;
            *reinterpret_cast<uint4*>(lp)     = make_uint4(lij[0], lij[1], lij[2], lij[3]);
            *reinterpret_cast<uint4*>(lp + 8) = make_uint4(lij[4], lij[5], lij[6], lij[7]);
            *reinterpret_cast<uint4*>(sBh + b_row0 * ROWH + b_seg0 * 8) = bvh[0];
            *reinterpret_cast<uint4*>(sBh + b_row1 * ROWH + b_seg1 * 8) = bvh[1];
            *reinterpret_cast<uint4*>(sBl + b_row0 * ROWH + b_seg0 * 8) = bvl[0];
            *reinterpret_cast<uint4*>(sBl + b_row1 * ROWH + b_seg1 * 8) = bvl[1];
        }
        __syncthreads();

        // ---- prefetch chunk c+1 into regs ----
        if (c + 1 < NCHK) {
            const int k0 = (c + 1) * 32;
            const float* xp = (arow >= 0) ? (X + arow * (long)D + k0 + a_kh) : nullptr;
#pragma unroll
            for (int j = 0; j < 4; j++)
                av[j] = xp ? *reinterpret_cast<const float4*>(xp + j * 4)
                           : make_float4(0.f, 0.f, 0.f, 0.f);
            bvh[0] = *reinterpret_cast<const uint4*>(BhG + (size_t)(n0 + b_row0) * 512 + k0 + b_seg0 * 8);
            bvh[1] = *reinterpret_cast<const uint4*>(BhG + (size_t)(n0 + b_row1) * 512 + k0 + b_seg1 * 8);
            bvl[0] = *reinterpret_cast<const uint4*>(BlG + (size_t)(n0 + b_row0) * 512 + k0 + b_seg0 * 8);
            bvl[1] = *reinterpret_cast<const uint4*>(BlG + (size_t)(n0 + b_row1) * 512 + k0 + b_seg1 * 8);
        }

        // ---- compute 2 k16 steps on buffer p ----
        const uint32_t bufb = s32 + p * BUFB;
#pragma unroll
        for (int kk = 0; kk < 2; kk++) {
            const int ko = kk * 16;
            uint32_t bh[4][2], bl[4][2];
#pragma unroll
            for (int pr = 0; pr < 2; pr++) {
                uint32_t addr = bufb + 2 * MATB * 2 +
                    ((ncol0 + pr * 16 + b_nl) * ROWH + ko + b_kl) * 2;
                ldm_x4(bh[pr * 2][0], bh[pr * 2][1], bh[pr * 2 + 1][0], bh[pr * 2 + 1][1], addr);
                ldm_x4(bl[pr * 2][0], bl[pr * 2][1], bl[pr * 2 + 1][0], bl[pr * 2 + 1][1],
                       addr + MATB * 2);
            }
#pragma unroll
            for (int mt = 0; mt < 4; mt++) {
                uint32_t ah[4], al[4];
                uint32_t addr = bufb + ((mrow0 + mt * 16 + a_rl) * ROWH + ko + a_kl) * 2;
                ldm_x4(ah[0], ah[1], ah[2], ah[3], addr);
                ldm_x4(al[0], al[1], al[2], al[3], addr + MATB * 2);
#pragma unroll
                for (int nt = 0; nt < 4; nt++) {
                    mma16816(acc[mt][nt], ah, bh[nt]);
                    mma16816(acc[mt][nt], ah, bl[nt]);
                    mma16816(acc[mt][nt], al, bh[nt]);
                }
            }
        }
        __syncthreads();
    }

    // ---------------- epilogue ----------------
    float* Y = (MODE == 0) ? g_h : g_A;
    const float* bias = (MODE == 0) ? (biasBase + lvl * D) : biasBase;  // MODE1: null
    const int cq = 2 * (lane & 3);
    const int rq = lane >> 2;
#pragma unroll
    for (int mt = 0; mt < 4; mt++) {
        const int r0 = m0 + mrow0 + mt * 16 + rq;
        const int r1 = r0 + 8;
        long gr0 = -1, gr1 = -1;
        if (r0 < cnt) gr0 = (MODE == 0) ? (long)g_perm[base + r0] : (long)r0;
        if (r1 < cnt) gr1 = (MODE == 0) ? (long)g_perm[base + r1] : (long)r1;
#pragma unroll
        for (int nt = 0; nt < 4; nt++) {
            const int col = n0 + ncol0 + nt * 8 + cq;
            float b0 = 0.f, b1 = 0.f;
            if (MODE != 1) { b0 = bias[col]; b1 = bias[col + 1]; }
            if (gr0 >= 0) {
                float2 v = make_float2(acc[mt][nt][0] + b0, acc[mt][nt][1] + b1);
                *reinterpret_cast<float2*>(Y + gr0 * (long)D + col) = v;
            }
            if (gr1 >= 0) {
                float2 v = make_float2(acc[mt][nt][2] + b0, acc[mt][nt][3] + b1);
                *reinterpret_cast<float2*>(Y + gr1 * (long)D + col) = v;
            }
        }
    }
}

// ---------------- level means -------------------------------------------------
__global__ void means_kernel() {
    const int col = blockIdx.x * 128 + threadIdx.x;
    const int lvl = blockIdx.y;
    const int cnt = g_counts[lvl];
    const int nsplit = gridDim.z;
    const int per = (cnt + nsplit - 1) / nsplit;
    const int j0 = blockIdx.z * per;
    const int j1 = min(j0 + per, cnt);
    const int off = g_offs[lvl];
    float acc = 0.f;
    for (int j = j0; j < j1; j++)
        acc += g_h[(size_t)g_perm[off + j] * D + col];
    if (j1 > j0) atomicAdd(&g_means[lvl * D + col], acc);
}
__global__ void finalize_means_kernel() {
    int idx = blockIdx.x * blockDim.x + threadIdx.x;
    if (idx < L * D) {
        int lvl = idx / D;
        g_means[idx] /= (float)max(g_counts[lvl], 1);
    }
}
__global__ void bb_kernel(const float* __restrict__ W1b, const float* __restrict__ b1) {
    const int lvl = blockIdx.y;
    const int j = blockIdx.x * 128 + threadIdx.x;
    float s = b1[j];
    for (int k = 0; k < D; k++)
        s = fmaf(g_means[lvl * D + k], W1b[(size_t)k * D + j], s);
    g_Bb[lvl * D + j] = s;
}

// ---------------- scoring + softmax + enhanced ---------------------------------
__global__ void __launch_bounds__(256) score_enhance_kernel(const float* __restrict__ w2) {
    __shared__ float sBb[L * D];
    __shared__ float sM[L * D];
    __shared__ int scnt[L];
    for (int i = threadIdx.x; i < L * D; i += 256) { sBb[i] = g_Bb[i]; sM[i] = g_means[i]; }
    if (threadIdx.x < L) scnt[threadIdx.x] = g_counts[threadIdx.x];
    __syncthreads();

    const int warp = threadIdx.x >> 5;
    const int lane = threadIdx.x & 31;
    float w[16];
#pragma unroll
    for (int j = 0; j < 16; j++) w[j] = w2[lane + j * 32];

    for (int it = 0; it < 4; it++) {
        const int node = blockIdx.x * 32 + warp * 4 + it;
        float a[16];
#pragma unroll
        for (int j = 0; j < 16; j++)
            a[j] = g_A[(size_t)node * D + lane + j * 32];
        float sc[L];
#pragma unroll
        for (int l = 0; l < L; l++) {
            float s = 0.f;
#pragma unroll
            for (int j = 0; j < 16; j++) {
                float x = a[j] + sBb[l * D + lane + j * 32];
                s = fmaf(w[j], tanh_fast(x), s);
            }
#pragma unroll
            for (int o = 16; o > 0; o >>= 1) s += __shfl_xor_sync(0xffffffffu, s, o);
            sc[l] = s;
        }
        float mx = -INFINITY;
#pragma unroll
        for (int l = 0; l < L; l++)
            if (scnt[l] > 0 && sc[l] > mx) mx = sc[l];
        float wt[L], ssum = 0.f;
#pragma unroll
        for (int l = 0; l < L; l++) {
            wt[l] = (scnt[l] > 0) ? __expf(sc[l] - mx) : 0.f;
            ssum += wt[l];
        }
        const float inv = 1.f / ssum;
#pragma unroll
        for (int j = 0; j < 16; j++) {
            int col = lane + j * 32;
            float e = 0.f;
#pragma unroll
            for (int l = 0; l < L; l++)
                e = fmaf(wt[l], sM[l * D + col], e);
            g_h[(size_t)node * D + col] = e * inv;
        }
    }
}

// ---------------- LayerNorm + ReLU ------------------------------------------
__global__ void __launch_bounds__(128) ln_kernel(const float* __restrict__ gamma,
                                                 const float* __restrict__ beta,
                                                 float* __restrict__ out) {
    const int row = blockIdx.x;
    const int t = threadIdx.x;
    float v[4];
    float s = 0.f, s2 = 0.f;
#pragma unroll
    for (int j = 0; j < 4; j++) {
        v[j] = g_A[(size_t)row * D + t + j * 128];
        s += v[j];
        s2 = fmaf(v[j], v[j], s2);
    }
    __shared__ float rs[8];
#pragma unroll
    for (int o = 16; o > 0; o >>= 1) {
        s  += __shfl_xor_sync(0xffffffffu, s, o);
        s2 += __shfl_xor_sync(0xffffffffu, s2, o);
    }
    int w = t >> 5;
    if ((t & 31) == 0) { rs[w] = s; rs[4 + w] = s2; }
    __syncthreads();
    s  = rs[0] + rs[1] + rs[2] + rs[3];
    s2 = rs[4] + rs[5] + rs[6] + rs[7];
    const float mu = s * (1.f / D);
    float var = s2 * (1.f / D) - mu * mu;
    var = fmaxf(var, 0.f);
    const float rstd = rsqrtf(var + LN_EPS);
#pragma unroll
    for (int j = 0; j < 4; j++) {
        int c = t + j * 128;
        float o = (v[j] - mu) * rstd * gamma[c] + beta[c];
        out[(size_t)row * D + c] = fmaxf(o, 0.f);
    }
}

// ---------------- launch --------------------------------------------------------
extern "C" void kernel_launch(void* const* d_in, const int* in_sizes, int n_in,
                              void* d_out, int out_size) {
    const float* x      = (const float*)d_in[0];
    const int*   levels = (const int*)  d_in[1];
    const float* W_proj = (const float*)d_in[2];
    const float* b_proj = (const float*)d_in[3];
    const float* W1a    = (const float*)d_in[4];
    const float* W1b    = (const float*)d_in[5];
    const float* b1     = (const float*)d_in[6];
    const float* w2     = (const float*)d_in[7];
    const float* Wout   = (const float*)d_in[9];
    const float* bout   = (const float*)d_in[10];
    const float* gamma  = (const float*)d_in[11];
    const float* beta   = (const float*)d_in[12];
    float* out = (float*)d_out;

    cudaFuncSetAttribute(gemm_hmma<0>, cudaFuncAttributeMaxDynamicSharedMemorySize, SMEM_TOT);
    cudaFuncSetAttribute(gemm_hmma<1>, cudaFuncAttributeMaxDynamicSharedMemorySize, SMEM_TOT);
    cudaFuncSetAttribute(gemm_hmma<2>, cudaFuncAttributeMaxDynamicSharedMemorySize, SMEM_TOT);

    reset_kernel<<<16, 256>>>();
    hist_kernel<<<N_NODES / 256, 256>>>(levels);
    scan_kernel<<<1, 1>>>();
    scatter_kernel<<<N_NODES / 256, 256>>>(levels);
    prep_b_kernel<<<(10 * 262144) / 256, 256>>>(W_proj, W1a, Wout);

    // h = x @ W_proj[lvl] + b_proj[lvl]   (grouped, gathered rows)
    gemm_hmma<0><<<dim3(4, 256, L), 256, SMEM_TOT>>>(x, b_proj);

    means_kernel<<<dim3(4, 8, 8), 128>>>();
    finalize_means_kernel<<<16, 256>>>();
    bb_kernel<<<dim3(4, 8), 128>>>(W1b, b1);

    // A = h @ W1a
    gemm_hmma<1><<<dim3(4, 256, 1), 256, SMEM_TOT>>>(nullptr, nullptr);

    // scores -> softmax -> enhanced (into g_h)
    score_enhance_kernel<<<N_NODES / 32, 256>>>(w2);

    // o = enhanced @ Wout + bout (into g_A)
    gemm_hmma<2><<<dim3(4, 256, 1), 256, SMEM_TOT>>>(nullptr, bout);

    // LayerNorm + ReLU -> out
    ln_kernel<<<N_NODES, 128>>>(gamma, beta, out);
}

// round 7
// speedup vs baseline: 1.5114x; 1.5114x over previous
#include <cuda_runtime.h>
#include <cuda_bf16.h>
#include <cstdint>
#include <math.h>

#define N_NODES 32768
#define D 512
#define L 8
#define LN_EPS 1e-5f

// ---------------- helpers ----------------------------------------------------
__device__ __forceinline__ uint32_t smem_u32(const void* p) {
    uint32_t a;
    asm("{ .reg .u64 t; cvta.to.shared.u64 t, %1; cvt.u32.u64 %0, t; }" : "=r"(a) : "l"(p));
    return a;
}
__device__ __forceinline__ uint32_t pbf2(float lo, float hi) {  // lo -> bits[0:16)
    uint32_t r;
    asm("cvt.rn.bf16x2.f32 %0, %1, %2;" : "=r"(r) : "f"(hi), "f"(lo));
    return r;
}
__device__ __forceinline__ float tanh_fast(float x) {
    float y;
    asm("tanh.approx.f32 %0, %1;" : "=f"(y) : "f"(x));
    return y;
}
__device__ __forceinline__ void ldm_x4(uint32_t& r0, uint32_t& r1, uint32_t& r2,
                                       uint32_t& r3, uint32_t addr) {
    asm volatile("ldmatrix.sync.aligned.m8n8.x4.shared.b16 {%0,%1,%2,%3}, [%4];"
                 : "=r"(r0), "=r"(r1), "=r"(r2), "=r"(r3) : "r"(addr));
}
__device__ __forceinline__ void mma16816(float* d, const uint32_t* a, const uint32_t* b) {
    asm volatile(
        "mma.sync.aligned.m16n8k16.row.col.f32.bf16.bf16.f32 "
        "{%0,%1,%2,%3}, {%4,%5,%6,%7}, {%8,%9}, {%0,%1,%2,%3};"
        : "+f"(d[0]), "+f"(d[1]), "+f"(d[2]), "+f"(d[3])
        : "r"(a[0]), "r"(a[1]), "r"(a[2]), "r"(a[3]), "r"(b[0]), "r"(b[1]));
}

// ---------------- scratch -----------------------------------------------------
__device__ __align__(16) float g_h[(size_t)N_NODES * D];
__device__ __align__(16) float g_A[(size_t)N_NODES * D];
__device__ int   g_perm[N_NODES];
__device__ int   g_counts[L];
__device__ int   g_offs[L];
__device__ int   g_cursor[L];
__device__ float g_means[L * D];
__device__ float g_Bb[L * D];
// pre-transposed bf16 weight halves: [mat][n][k], mat 0..7 proj, 8 W1a, 9 Wout
__device__ __align__(16) __nv_bfloat16 g_bth[10 * 512 * 512];
__device__ __align__(16) __nv_bfloat16 g_btl[10 * 512 * 512];

// ---------------- bucketing ----------------------------------------------------
__global__ void reset_kernel() {
    int idx = blockIdx.x * blockDim.x + threadIdx.x;
    if (idx < L) g_counts[idx] = 0;
    if (idx < L * D) g_means[idx] = 0.f;
}
__global__ void hist_kernel(const int* __restrict__ levels) {
    __shared__ int h[L];
    if (threadIdx.x < L) h[threadIdx.x] = 0;
    __syncthreads();
    int i = blockIdx.x * blockDim.x + threadIdx.x;
    if (i < N_NODES) atomicAdd(&h[levels[i]], 1);
    __syncthreads();
    if (threadIdx.x < L) atomicAdd(&g_counts[threadIdx.x], h[threadIdx.x]);
}
__global__ void scan_kernel() {
    int o = 0;
    for (int l = 0; l < L; l++) { g_offs[l] = o; g_cursor[l] = o; o += g_counts[l]; }
}
__global__ void scatter_kernel(const int* __restrict__ levels) {
    int i = blockIdx.x * blockDim.x + threadIdx.x;
    if (i < N_NODES) {
        int p = atomicAdd(&g_cursor[levels[i]], 1);
        g_perm[p] = i;
    }
}

// ---------------- weight prep: transpose + bf16 split ---------------------------
__global__ void prep_b_kernel(const float* __restrict__ Wp,
                              const float* __restrict__ W1a,
                              const float* __restrict__ Wout) {
    int idx = blockIdx.x * 256 + threadIdx.x;
    if (idx >= 10 * 262144) return;
    int mat = idx >> 18;
    int rem = idx & 262143;
    int n = rem >> 9;
    int k = rem & 511;
    const float* src = (mat < 8) ? (Wp + ((size_t)mat << 18)) : (mat == 8 ? W1a : Wout);
    float v = src[(size_t)k * 512 + n];
    __nv_bfloat16 h = __float2bfloat16(v);
    g_bth[idx] = h;
    g_btl[idx] = __float2bfloat16(v - __bfloat162float(h));
}

// ---------------- HMMA GEMM: Y[M x 512] = X[M x 512] @ W (bf16 split) ----------
// MODE 0: grouped per level: X = node_features gathered via perm, +b_proj[l] -> g_h
// MODE 1: X = g_h @ W1a -> g_A
// MODE 2: X = g_h @ Wout + bout -> g_A (LN done separately)
#define NCHK 16          // 512 / 32
#define ROWH 40          // 32 + 8 pad halves per smem row
#define MATB (128 * ROWH)       // halves per matrix
#define BUFB (4 * MATB * 2)     // bytes per buffer (Ah, Al, Bh, Bl)
#define SMEM_TOT (2 * BUFB)     // 81920 bytes

template <int MODE>
__global__ void __launch_bounds__(256, 1)
gemm_hmma(const float* __restrict__ Xin, const float* __restrict__ biasBase)
{
    const int lvl  = (MODE == 0) ? blockIdx.z : 0;
    const int cnt  = (MODE == 0) ? g_counts[lvl] : N_NODES;
    const int base = (MODE == 0) ? g_offs[lvl] : 0;
    const int m0 = blockIdx.y * 128;
    if (m0 >= cnt) return;
    const int n0 = blockIdx.x * 128;

    extern __shared__ __align__(16) char smem[];
    __nv_bfloat16* s = reinterpret_cast<__nv_bfloat16*>(smem);
    const uint32_t s32 = smem_u32(smem);

    const int t = threadIdx.x;
    const int wid = t >> 5, lane = t & 31;

    const int mat = (MODE == 0) ? lvl : (MODE == 1 ? 8 : 9);
    const __nv_bfloat16* __restrict__ BhG = g_bth + ((size_t)mat << 18);
    const __nv_bfloat16* __restrict__ BlG = g_btl + ((size_t)mat << 18);
    const float* __restrict__ X = (MODE == 0) ? Xin : g_h;

    // A-load mapping: thread pair per row
    const int a_row = t >> 1;
    const int a_kh  = (t & 1) * 16;
    long arow = -1;
    if (m0 + a_row < cnt)
        arow = (MODE == 0) ? (long)g_perm[base + m0 + a_row] : (long)(m0 + a_row);

    // B-load mapping: idx -> (row n, 16B seg)
    const int b_row0 = (t + 0)   >> 2, b_seg0 = (t + 0)   & 3;
    const int b_row1 = (t + 256) >> 2, b_seg1 = (t + 256) & 3;

    // warp tiles
    const int mrow0 = (wid >> 2) * 64;
    const int ncol0 = (wid & 3) * 32;
    // ldmatrix lane addressing components
    const int a_rl = lane & 15;
    const int a_kl = (lane >> 4) * 8;
    const int b_nl = (lane >> 4) * 8 + (lane & 7);
    const int b_kl = ((lane >> 3) & 1) * 8;

    float acc[4][4][4];
#pragma unroll
    for (int i = 0; i < 4; i++)
#pragma unroll
        for (int j = 0; j < 4; j++)
#pragma unroll
            for (int q = 0; q < 4; q++) acc[i][j][q] = 0.f;

    float4 av[4];
    uint4 bvh[2], bvl[2];

    // ---- load chunk 0 into regs ----
    {
        const float* xp = (arow >= 0) ? (X + arow * (long)D + a_kh) : nullptr;
#pragma unroll
        for (int j = 0; j < 4; j++)
            av[j] = xp ? *reinterpret_cast<const float4*>(xp + j * 4)
                       : make_float4(0.f, 0.f, 0.f, 0.f);
        bvh[0] = *reinterpret_cast<const uint4*>(BhG + (size_t)(n0 + b_row0) * 512 + b_seg0 * 8);
        bvh[1] = *reinterpret_cast<const uint4*>(BhG + (size_t)(n0 + b_row1) * 512 + b_seg1 * 8);
        bvl[0] = *reinterpret_cast<const uint4*>(BlG + (size_t)(n0 + b_row0) * 512 + b_seg0 * 8);
        bvl[1] = *reinterpret_cast<const uint4*>(BlG + (size_t)(n0 + b_row1) * 512 + b_seg1 * 8);
    }

    for (int c = 0; c < NCHK; c++) {
        const int p = c & 1;
        __nv_bfloat16* sAh = s + p * (4 * MATB);
        __nv_bfloat16* sAl = sAh + MATB;
        __nv_bfloat16* sBh = sAh + 2 * MATB;
        __nv_bfloat16* sBl = sAh + 3 * MATB;

        // ---- store regs (chunk c) into buffer p ----
        {
            uint32_t hij[8], lij[8];
#pragma unroll
            for (int j = 0; j < 4; j++) {
                float4 v = av[j];
                float hx = __bfloat162float(__float2bfloat16(v.x));
                float hy = __bfloat162float(__float2bfloat16(v.y));
                float hz = __bfloat162float(__float2bfloat16(v.z));
                float hw = __bfloat162float(__float2bfloat16(v.w));
                hij[j * 2 + 0] = pbf2(hx, hy);
                hij[j * 2 + 1] = pbf2(hz, hw);
                lij[j * 2 + 0] = pbf2(v.x - hx, v.y - hy);
                lij[j * 2 + 1] = pbf2(v.z - hz, v.w - hw);
            }
            __nv_bfloat16* ap = sAh + a_row * ROWH + a_kh;
            *reinterpret_cast<uint4*>(ap)     = make_uint4(hij[0], hij[1], hij[2], hij[3]);
            *reinterpret_cast<uint4*>(ap + 8) = make_uint4(hij[4], hij[5], hij[6], hij[7]);
            __nv_bfloat16* lp = sAl + a_row * ROWH + a_kh;
            *reinterpret_cast<uint4*>(lp)     = make_uint4(lij[0], lij[1], lij[2], lij[3]);
            *reinterpret_cast<uint4*>(lp + 8) = make_uint4(lij[4], lij[5], lij[6], lij[7]);
            *reinterpret_cast<uint4*>(sBh + b_row0 * ROWH + b_seg0 * 8) = bvh[0];
            *reinterpret_cast<uint4*>(sBh + b_row1 * ROWH + b_seg1 * 8) = bvh[1];
            *reinterpret_cast<uint4*>(sBl + b_row0 * ROWH + b_seg0 * 8) = bvl[0];
            *reinterpret_cast<uint4*>(sBl + b_row1 * ROWH + b_seg1 * 8) = bvl[1];
        }
        __syncthreads();

        // ---- prefetch chunk c+1 into regs ----
        if (c + 1 < NCHK) {
            const int k0 = (c + 1) * 32;
            const float* xp = (arow >= 0) ? (X + arow * (long)D + k0 + a_kh) : nullptr;
#pragma unroll
            for (int j = 0; j < 4; j++)
                av[j] = xp ? *reinterpret_cast<const float4*>(xp + j * 4)
                           : make_float4(0.f, 0.f, 0.f, 0.f);
            bvh[0] = *reinterpret_cast<const uint4*>(BhG + (size_t)(n0 + b_row0) * 512 + k0 + b_seg0 * 8);
            bvh[1] = *reinterpret_cast<const uint4*>(BhG + (size_t)(n0 + b_row1) * 512 + k0 + b_seg1 * 8);
            bvl[0] = *reinterpret_cast<const uint4*>(BlG + (size_t)(n0 + b_row0) * 512 + k0 + b_seg0 * 8);
            bvl[1] = *reinterpret_cast<const uint4*>(BlG + (size_t)(n0 + b_row1) * 512 + k0 + b_seg1 * 8);
        }

        // ---- compute 2 k16 steps on buffer p ----
        const uint32_t bufb = s32 + p * BUFB;
#pragma unroll
        for (int kk = 0; kk < 2; kk++) {
            const int ko = kk * 16;
            uint32_t bh[4][2], bl[4][2];
#pragma unroll
            for (int pr = 0; pr < 2; pr++) {
                uint32_t addr = bufb + 2 * MATB * 2 +
                    ((ncol0 + pr * 16 + b_nl) * ROWH + ko + b_kl) * 2;
                ldm_x4(bh[pr * 2][0], bh[pr * 2][1], bh[pr * 2 + 1][0], bh[pr * 2 + 1][1], addr);
                ldm_x4(bl[pr * 2][0], bl[pr * 2][1], bl[pr * 2 + 1][0], bl[pr * 2 + 1][1],
                       addr + MATB * 2);
            }
#pragma unroll
            for (int mt = 0; mt < 4; mt++) {
                uint32_t ah[4], al[4];
                uint32_t addr = bufb + ((mrow0 + mt * 16 + a_rl) * ROWH + ko + a_kl) * 2;
                ldm_x4(ah[0], ah[1], ah[2], ah[3], addr);
                ldm_x4(al[0], al[1], al[2], al[3], addr + MATB * 2);
#pragma unroll
                for (int nt = 0; nt < 4; nt++) {
                    mma16816(acc[mt][nt], ah, bh[nt]);
                    mma16816(acc[mt][nt], ah, bl[nt]);
                    mma16816(acc[mt][nt], al, bh[nt]);
                }
            }
        }
        __syncthreads();
    }

    // ---------------- epilogue ----------------
    float* Y = (MODE == 0) ? g_h : g_A;
    const float* bias = (MODE == 0) ? (biasBase + lvl * D) : biasBase;  // MODE1: null
    const int cq = 2 * (lane & 3);
    const int rq = lane >> 2;
#pragma unroll
    for (int mt = 0; mt < 4; mt++) {
        const int r0 = m0 + mrow0 + mt * 16 + rq;
        const int r1 = r0 + 8;
        long gr0 = -1, gr1 = -1;
        if (r0 < cnt) gr0 = (MODE == 0) ? (long)g_perm[base + r0] : (long)r0;
        if (r1 < cnt) gr1 = (MODE == 0) ? (long)g_perm[base + r1] : (long)r1;
#pragma unroll
        for (int nt = 0; nt < 4; nt++) {
            const int col = n0 + ncol0 + nt * 8 + cq;
            float b0 = 0.f, b1 = 0.f;
            if (MODE != 1) { b0 = bias[col]; b1 = bias[col + 1]; }
            if (gr0 >= 0) {
                float2 v = make_float2(acc[mt][nt][0] + b0, acc[mt][nt][1] + b1);
                *reinterpret_cast<float2*>(Y + gr0 * (long)D + col) = v;
            }
            if (gr1 >= 0) {
                float2 v = make_float2(acc[mt][nt][2] + b0, acc[mt][nt][3] + b1);
                *reinterpret_cast<float2*>(Y + gr1 * (long)D + col) = v;
            }
        }
    }
}

// ---------------- level means -------------------------------------------------
__global__ void means_kernel() {
    const int col = blockIdx.x * 128 + threadIdx.x;
    const int lvl = blockIdx.y;
    const int cnt = g_counts[lvl];
    const int nsplit = gridDim.z;
    const int per = (cnt + nsplit - 1) / nsplit;
    const int j0 = blockIdx.z * per;
    const int j1 = min(j0 + per, cnt);
    const int off = g_offs[lvl];
    float acc = 0.f;
    for (int j = j0; j < j1; j++)
        acc += g_h[(size_t)g_perm[off + j] * D + col];
    if (j1 > j0) atomicAdd(&g_means[lvl * D + col], acc);
}
__global__ void finalize_means_kernel() {
    int idx = blockIdx.x * blockDim.x + threadIdx.x;
    if (idx < L * D) {
        int lvl = idx / D;
        g_means[idx] /= (float)max(g_counts[lvl], 1);
    }
}
__global__ void bb_kernel(const float* __restrict__ W1b, const float* __restrict__ b1) {
    const int lvl = blockIdx.y;
    const int j = blockIdx.x * 128 + threadIdx.x;
    float s = b1[j];
    for (int k = 0; k < D; k++)
        s = fmaf(g_means[lvl * D + k], W1b[(size_t)k * D + j], s);
    g_Bb[lvl * D + j] = s;
}

// ---------------- scoring + softmax + enhanced ---------------------------------
__global__ void __launch_bounds__(256) score_enhance_kernel(const float* __restrict__ w2) {
    __shared__ float sBb[L * D];
    __shared__ float sM[L * D];
    __shared__ int scnt[L];
    for (int i = threadIdx.x; i < L * D; i += 256) { sBb[i] = g_Bb[i]; sM[i] = g_means[i]; }
    if (threadIdx.x < L) scnt[threadIdx.x] = g_counts[threadIdx.x];
    __syncthreads();

    const int warp = threadIdx.x >> 5;
    const int lane = threadIdx.x & 31;
    float w[16];
#pragma unroll
    for (int j = 0; j < 16; j++) w[j] = w2[lane + j * 32];

    for (int it = 0; it < 4; it++) {
        const int node = blockIdx.x * 32 + warp * 4 + it;
        float a[16];
#pragma unroll
        for (int j = 0; j < 16; j++)
            a[j] = g_A[(size_t)node * D + lane + j * 32];
        float sc[L];
#pragma unroll
        for (int l = 0; l < L; l++) {
            float s = 0.f;
#pragma unroll
            for (int j = 0; j < 16; j++) {
                float x = a[j] + sBb[l * D + lane + j * 32];
                s = fmaf(w[j], tanh_fast(x), s);
            }
#pragma unroll
            for (int o = 16; o > 0; o >>= 1) s += __shfl_xor_sync(0xffffffffu, s, o);
            sc[l] = s;
        }
        float mx = -INFINITY;
#pragma unroll
        for (int l = 0; l < L; l++)
            if (scnt[l] > 0 && sc[l] > mx) mx = sc[l];
        float wt[L], ssum = 0.f;
#pragma unroll
        for (int l = 0; l < L; l++) {
            wt[l] = (scnt[l] > 0) ? __expf(sc[l] - mx) : 0.f;
            ssum += wt[l];
        }
        const float inv = 1.f / ssum;
#pragma unroll
        for (int j = 0; j < 16; j++) {
            int col = lane + j * 32;
            float e = 0.f;
#pragma unroll
            for (int l = 0; l < L; l++)
                e = fmaf(wt[l], sM[l * D + col], e);
            g_h[(size_t)node * D + col] = e * inv;
        }
    }
}

// ---------------- LayerNorm + ReLU ------------------------------------------
__global__ void __launch_bounds__(128) ln_kernel(const float* __restrict__ gamma,
                                                 const float* __restrict__ beta,
                                                 float* __restrict__ out) {
    const int row = blockIdx.x;
    const int t = threadIdx.x;
    float v[4];
    float s = 0.f, s2 = 0.f;
#pragma unroll
    for (int j = 0; j < 4; j++) {
        v[j] = g_A[(size_t)row * D + t + j * 128];
        s += v[j];
        s2 = fmaf(v[j], v[j], s2);
    }
    __shared__ float rs[8];
#pragma unroll
    for (int o = 16; o > 0; o >>= 1) {
        s  += __shfl_xor_sync(0xffffffffu, s, o);
        s2 += __shfl_xor_sync(0xffffffffu, s2, o);
    }
    int w = t >> 5;
    if ((t & 31) == 0) { rs[w] = s; rs[4 + w] = s2; }
    __syncthreads();
    s  = rs[0] + rs[1] + rs[2] + rs[3];
    s2 = rs[4] + rs[5] + rs[6] + rs[7];
    const float mu = s * (1.f / D);
    float var = s2 * (1.f / D) - mu * mu;
    var = fmaxf(var, 0.f);
    const float rstd = rsqrtf(var + LN_EPS);
#pragma unroll
    for (int j = 0; j < 4; j++) {
        int c = t + j * 128;
        float o = (v[j] - mu) * rstd * gamma[c] + beta[c];
        out[(size_t)row * D + c] = fmaxf(o, 0.f);
    }
}

// ---------------- launch --------------------------------------------------------
extern "C" void kernel_launch(void* const* d_in, const int* in_sizes, int n_in,
                              void* d_out, int out_size) {
    const float* x      = (const float*)d_in[0];
    const int*   levels = (const int*)  d_in[1];
    const float* W_proj = (const float*)d_in[2];
    const float* b_proj = (const float*)d_in[3];
    const float* W1a    = (const float*)d_in[4];
    const float* W1b    = (const float*)d_in[5];
    const float* b1     = (const float*)d_in[6];
    const float* w2     = (const float*)d_in[7];
    const float* Wout   = (const float*)d_in[9];
    const float* bout   = (const float*)d_in[10];
    const float* gamma  = (const float*)d_in[11];
    const float* beta   = (const float*)d_in[12];
    float* out = (float*)d_out;

    cudaFuncSetAttribute(gemm_hmma<0>, cudaFuncAttributeMaxDynamicSharedMemorySize, SMEM_TOT);
    cudaFuncSetAttribute(gemm_hmma<1>, cudaFuncAttributeMaxDynamicSharedMemorySize, SMEM_TOT);
    cudaFuncSetAttribute(gemm_hmma<2>, cudaFuncAttributeMaxDynamicSharedMemorySize, SMEM_TOT);

    reset_kernel<<<16, 256>>>();
    hist_kernel<<<N_NODES / 256, 256>>>(levels);
    scan_kernel<<<1, 1>>>();
    scatter_kernel<<<N_NODES / 256, 256>>>(levels);
    prep_b_kernel<<<(10 * 262144) / 256, 256>>>(W_proj, W1a, Wout);

    // h = x @ W_proj[lvl] + b_proj[lvl]   (grouped, gathered rows)
    gemm_hmma<0><<<dim3(4, 256, L), 256, SMEM_TOT>>>(x, b_proj);

    means_kernel<<<dim3(4, 8, 8), 128>>>();
    finalize_means_kernel<<<16, 256>>>();
    bb_kernel<<<dim3(4, 8), 128>>>(W1b, b1);

    // A = h @ W1a
    gemm_hmma<1><<<dim3(4, 256, 1), 256, SMEM_TOT>>>(nullptr, nullptr);

    // scores -> softmax -> enhanced (into g_h)
    score_enhance_kernel<<<N_NODES / 32, 256>>>(w2);

    // o = enhanced @ Wout + bout (into g_A)
    gemm_hmma<2><<<dim3(4, 256, 1), 256, SMEM_TOT>>>(nullptr, bout);

    // LayerNorm + ReLU -> out
    ln_kernel<<<N_NODES, 128>>>(gamma, beta, out);
}